// round 1
// baseline (speedup 1.0000x reference)
#include <cuda_runtime.h>
#include <math.h>

#define BB 4
#define SS 2048
#define EE 512
#define HH 8
#define DD 64

// Scratch (allocation-free requirement -> __device__ globals)
__device__ float g_qp[BB * HH * SS * DD];  // [B,H,S,D]
__device__ float g_kp[BB * HH * SS * DD];
__device__ float g_vp[BB * HH * SS * DD];
__device__ float g_o [BB * SS * EE];       // attention output, [B,S,E]

// ---------------------------------------------------------------------------
// Kernel 1: per-head projection  out[n,e] = sum_d x[n,d] * W[e,d]
// x viewed as rows n=(b*S+s)*H+h of 64 contiguous floats; out in [B,H,S,D].
// ---------------------------------------------------------------------------
__global__ void __launch_bounds__(256) proj_kernel(
    const float* __restrict__ x, const float* __restrict__ W, int which)
{
    float* out = (which == 0) ? g_qp : (which == 1) ? g_kp : g_vp;

    __shared__ float Wt[64 * 64];  // transposed: Wt[d*64+e] = W[e*64+d]
    __shared__ float xs[4 * 64];

    int t = threadIdx.x;
    for (int i = t; i < 4096; i += 256) {
        int e = i >> 6, d = i & 63;
        Wt[d * 64 + e] = W[i];
    }
    __syncthreads();

    int base_row = blockIdx.x * 256;   // 256 rows per block
    int rloc = t >> 6;                 // 0..3
    int e    = t & 63;

    for (int g = 0; g < 64; g++) {
        int row0 = base_row + g * 4;
        xs[t] = x[row0 * 64 + t];      // 4 full rows, coalesced
        __syncthreads();

        const float* xr = &xs[rloc * 64];
        float sum = 0.f;
#pragma unroll
        for (int d = 0; d < 64; d += 4) {
            float4 xv = *(const float4*)(&xr[d]);
            sum += xv.x * Wt[(d + 0) * 64 + e];
            sum += xv.y * Wt[(d + 1) * 64 + e];
            sum += xv.z * Wt[(d + 2) * 64 + e];
            sum += xv.w * Wt[(d + 3) * 64 + e];
        }
        int n   = row0 + rloc;           // (b*S+s)*H + h
        int b   = n >> 14;               // / (S*H) = /16384
        int rem = n & 16383;
        int s   = rem >> 3;              // / H
        int h   = rem & 7;
        out[(((b * HH + h) * SS) + s) * 64 + e] = sum;
        __syncthreads();
    }
}

// ---------------------------------------------------------------------------
// Kernel 2: flash attention, one query row per thread.
// grid: (S/128, B*H), block: 128. Q row + accumulator in registers.
// ---------------------------------------------------------------------------
#define BK 32

__global__ void __launch_bounds__(128) flash_kernel()
{
    __shared__ float Ks[BK][DD];
    __shared__ float Vs[BK][DD];

    int t     = threadIdx.x;
    int bh    = blockIdx.y;                 // b*H + h
    int q_row = blockIdx.x * 128 + t;

    const float* Qb = g_qp + (bh * SS + q_row) * DD;

    float q[DD];
#pragma unroll
    for (int d = 0; d < DD; d += 4) {
        float4 v = *(const float4*)(Qb + d);
        q[d] = v.x; q[d + 1] = v.y; q[d + 2] = v.z; q[d + 3] = v.w;
    }

    float acc[DD];
#pragma unroll
    for (int d = 0; d < DD; d++) acc[d] = 0.f;
    float m = -INFINITY, l = 0.f;

    // scale = 1/sqrt(512); fold in log2(e) so we can use exp2f
    const float cscale = 0.04419417382415922f * 1.4426950408889634f;

    const float* Kbase = g_kp + bh * SS * DD;
    const float* Vbase = g_vp + bh * SS * DD;

    for (int kt = 0; kt < SS / BK; kt++) {
        __syncthreads();
        const float* Kb = Kbase + kt * BK * DD;
        const float* Vb = Vbase + kt * BK * DD;
#pragma unroll
        for (int i = t * 4; i < BK * DD; i += 128 * 4) {
            *(float4*)(&Ks[0][0] + i) = *(const float4*)(Kb + i);
            *(float4*)(&Vs[0][0] + i) = *(const float4*)(Vb + i);
        }
        __syncthreads();

        float sc[BK];
#pragma unroll
        for (int j = 0; j < BK; j++) {
            float a0 = 0.f, a1 = 0.f, a2 = 0.f, a3 = 0.f;
#pragma unroll
            for (int d = 0; d < DD; d += 4) {
                float4 kv = *(const float4*)(&Ks[j][d]);  // warp-broadcast
                a0 += q[d    ] * kv.x;
                a1 += q[d + 1] * kv.y;
                a2 += q[d + 2] * kv.z;
                a3 += q[d + 3] * kv.w;
            }
            sc[j] = (a0 + a1) + (a2 + a3);
        }

        float mt = m;
#pragma unroll
        for (int j = 0; j < BK; j++) mt = fmaxf(mt, sc[j]);

        float alpha = exp2f((m - mt) * cscale);
        m = mt;

        float ls = 0.f;
#pragma unroll
        for (int j = 0; j < BK; j++) {
            sc[j] = exp2f((sc[j] - mt) * cscale);
            ls += sc[j];
        }
        l = l * alpha + ls;

#pragma unroll
        for (int d = 0; d < DD; d++) acc[d] *= alpha;

#pragma unroll
        for (int j = 0; j < BK; j++) {
            float p = sc[j];
#pragma unroll
            for (int d = 0; d < DD; d += 4) {
                float4 vv = *(const float4*)(&Vs[j][d]);  // warp-broadcast
                acc[d    ] += p * vv.x;
                acc[d + 1] += p * vv.y;
                acc[d + 2] += p * vv.z;
                acc[d + 3] += p * vv.w;
            }
        }
    }

    float inv = 1.f / l;
    int b = bh >> 3, h = bh & 7;
    float* Ob = g_o + ((b * SS + q_row) * EE) + h * 64;
#pragma unroll
    for (int d = 0; d < DD; d += 4) {
        float4 o4;
        o4.x = acc[d] * inv;  o4.y = acc[d + 1] * inv;
        o4.z = acc[d + 2] * inv; o4.w = acc[d + 3] * inv;
        *(float4*)(Ob + d) = o4;
    }
}

// ---------------------------------------------------------------------------
// Kernel 3: output projection  out = X @ Wo^T + bo
// X = g_o [8192, 512], Wo [512, 512]. 64x64 block tile, 4x4 per thread.
// ---------------------------------------------------------------------------
__global__ void __launch_bounds__(256) out_gemm_kernel(
    const float* __restrict__ Wo, const float* __restrict__ bo,
    float* __restrict__ out)
{
    __shared__ float As[16][64];
    __shared__ float Bs[16][64];

    int t  = threadIdx.x;
    int m0 = blockIdx.x * 64;
    int n0 = blockIdx.y * 64;
    int tm = (t >> 4) * 4;     // 0..60
    int tn = (t & 15) * 4;     // 0..60

    float acc[4][4];
#pragma unroll
    for (int i = 0; i < 4; i++)
#pragma unroll
        for (int j = 0; j < 4; j++) acc[i][j] = 0.f;

    const float* X = g_o;
    int lr = t >> 2;           // 0..63
    int lc = (t & 3) * 4;      // 0,4,8,12

    for (int k0 = 0; k0 < 512; k0 += 16) {
        __syncthreads();
        float4 a = *(const float4*)(X  + (m0 + lr) * 512 + k0 + lc);
        float4 b = *(const float4*)(Wo + (n0 + lr) * 512 + k0 + lc);
        As[lc + 0][lr] = a.x; As[lc + 1][lr] = a.y;
        As[lc + 2][lr] = a.z; As[lc + 3][lr] = a.w;
        Bs[lc + 0][lr] = b.x; Bs[lc + 1][lr] = b.y;
        Bs[lc + 2][lr] = b.z; Bs[lc + 3][lr] = b.w;
        __syncthreads();

#pragma unroll
        for (int k = 0; k < 16; k++) {
            float ar[4], br[4];
            *(float4*)ar = *(const float4*)(&As[k][tm]);
            *(float4*)br = *(const float4*)(&Bs[k][tn]);
#pragma unroll
            for (int i = 0; i < 4; i++)
#pragma unroll
                for (int j = 0; j < 4; j++)
                    acc[i][j] += ar[i] * br[j];
        }
    }

#pragma unroll
    for (int i = 0; i < 4; i++) {
        float4 o4;
        o4.x = acc[i][0] + bo[n0 + tn + 0];
        o4.y = acc[i][1] + bo[n0 + tn + 1];
        o4.z = acc[i][2] + bo[n0 + tn + 2];
        o4.w = acc[i][3] + bo[n0 + tn + 3];
        *(float4*)(out + (m0 + tm + i) * 512 + n0 + tn) = o4;
    }
}

// ---------------------------------------------------------------------------
// Launch.  Input order: values, keys, query, Wv, Wk, Wq, Wo, bo
// ---------------------------------------------------------------------------
extern "C" void kernel_launch(void* const* d_in, const int* in_sizes, int n_in,
                              void* d_out, int out_size)
{
    const float* values = (const float*)d_in[0];
    const float* keys   = (const float*)d_in[1];
    const float* query  = (const float*)d_in[2];
    const float* Wv     = (const float*)d_in[3];
    const float* Wk     = (const float*)d_in[4];
    const float* Wq     = (const float*)d_in[5];
    const float* Wo     = (const float*)d_in[6];
    const float* bo     = (const float*)d_in[7];
    float* out = (float*)d_out;

    proj_kernel<<<256, 256>>>(query,  Wq, 0);
    proj_kernel<<<256, 256>>>(keys,   Wk, 1);
    proj_kernel<<<256, 256>>>(values, Wv, 2);

    dim3 fgrid(SS / 128, BB * HH);
    flash_kernel<<<fgrid, 128>>>();

    dim3 ggrid((BB * SS) / 64, EE / 64);
    out_gemm_kernel<<<ggrid, 256>>>(Wo, bo, out);
}

// round 2
// speedup vs baseline: 1.4039x; 1.4039x over previous
#include <cuda_runtime.h>
#include <math.h>

#define BB 4
#define SS 2048
#define EE 512
#define HH 8
#define DD 64

// Scratch (allocation-free requirement -> __device__ globals)
__device__ float g_qp[BB * HH * SS * DD];  // [B,H,S,D]
__device__ float g_kp[BB * HH * SS * DD];
__device__ float g_vp[BB * HH * SS * DD];
__device__ float g_o [BB * SS * EE];       // attention output, [B,S,E]

// ---------------------------------------------------------------------------
// Kernel 1: per-head projection as a register-tiled GEMM.
// out[n,e] = sum_d x[n,d] * W[e,d];  64 rows per block, 256 threads,
// 4x4 register tile per thread.  Output scattered to [B,H,S,D].
// ---------------------------------------------------------------------------
__global__ void __launch_bounds__(256) proj_kernel(
    const float* __restrict__ x, const float* __restrict__ W, int which)
{
    float* out = (which == 0) ? g_qp : (which == 1) ? g_kp : g_vp;

    __shared__ float Xs[64][64];   // transposed: Xs[d][r]
    __shared__ float Wt[64][64];   // transposed: Wt[d][e]

    int t = threadIdx.x;
    int rbase = blockIdx.x * 64;

    // load x tile transposed + W transposed (both: thread row r=t>>2, 16 cols)
    {
        int r = t >> 2, cb = (t & 3) * 16;
        const float* xp = x + (rbase + r) * 64 + cb;
        const float* wp = W + r * 64 + cb;
#pragma unroll
        for (int xk = 0; xk < 4; xk++) {
            float4 v = *(const float4*)(xp + 4 * xk);
            int c = cb + 4 * xk;
            Xs[c + 0][r] = v.x; Xs[c + 1][r] = v.y;
            Xs[c + 2][r] = v.z; Xs[c + 3][r] = v.w;
            float4 w = *(const float4*)(wp + 4 * xk);
            Wt[c + 0][r] = w.x; Wt[c + 1][r] = w.y;
            Wt[c + 2][r] = w.z; Wt[c + 3][r] = w.w;
        }
    }
    __syncthreads();

    int tm = (t >> 4) * 4;   // row-offset within tile
    int tn = (t & 15) * 4;   // e-offset

    float acc[4][4];
#pragma unroll
    for (int a = 0; a < 4; a++)
#pragma unroll
        for (int b = 0; b < 4; b++) acc[a][b] = 0.f;

#pragma unroll
    for (int k = 0; k < 64; k++) {
        float4 ar = *(const float4*)(&Xs[k][tm]);
        float4 br = *(const float4*)(&Wt[k][tn]);
        acc[0][0] += ar.x * br.x; acc[0][1] += ar.x * br.y;
        acc[0][2] += ar.x * br.z; acc[0][3] += ar.x * br.w;
        acc[1][0] += ar.y * br.x; acc[1][1] += ar.y * br.y;
        acc[1][2] += ar.y * br.z; acc[1][3] += ar.y * br.w;
        acc[2][0] += ar.z * br.x; acc[2][1] += ar.z * br.y;
        acc[2][2] += ar.z * br.z; acc[2][3] += ar.z * br.w;
        acc[3][0] += ar.w * br.x; acc[3][1] += ar.w * br.y;
        acc[3][2] += ar.w * br.z; acc[3][3] += ar.w * br.w;
    }

#pragma unroll
    for (int mi = 0; mi < 4; mi++) {
        int n   = rbase + tm + mi;       // (b*S+s)*H + h
        int b   = n >> 14;
        int rem = n & 16383;
        int s   = rem >> 3;
        int h   = rem & 7;
        float4 o4;
        o4.x = acc[mi][0]; o4.y = acc[mi][1];
        o4.z = acc[mi][2]; o4.w = acc[mi][3];
        *(float4*)(out + (((b * HH + h) * SS) + s) * 64 + tn) = o4;
    }
}

// ---------------------------------------------------------------------------
// Kernel 2: flash attention v2, 64 q-rows per block, 256 threads,
// 4x4 register tiles, SHFL-based P broadcast for the PV GEMM.
// ---------------------------------------------------------------------------
__global__ void __launch_bounds__(256, 2) flash2_kernel()
{
    __shared__ float Qs[64][64];   // [d][m], xor-swizzled
    __shared__ float Ks[64][64];   // [d][n], xor-swizzled
    __shared__ float Vs[64][64];   // [kv][d], natural

    int t  = threadIdx.x;
    int bh = blockIdx.y;
    int q0 = blockIdx.x * 64;
    int m0 = (t >> 4) * 4;   // q-row offset (group of 16 lanes shares m0)
    int n0 = (t & 15) * 4;   // kv-col / d-col offset

    const float* Qb    = g_qp + (bh * SS + q0) * DD;
    const float* Kbase = g_kp + bh * SS * DD;
    const float* Vbase = g_vp + bh * SS * DD;

    // load Q tile transposed w/ swizzle: Qs[c][r ^ (((c>>4)&3)<<3)]
    {
        int r = t >> 2, cb = (t & 3) * 16;
        const float* qp = Qb + r * 64 + cb;
#pragma unroll
        for (int xk = 0; xk < 4; xk++) {
            float4 v = *(const float4*)(qp + 4 * xk);
            int c  = cb + 4 * xk;
            int rs = r ^ (((c >> 4) & 3) << 3);
            Qs[c + 0][rs] = v.x; Qs[c + 1][rs] = v.y;
            Qs[c + 2][rs] = v.z; Qs[c + 3][rs] = v.w;
        }
    }

    float acc[4][4];
#pragma unroll
    for (int a = 0; a < 4; a++)
#pragma unroll
        for (int b = 0; b < 4; b++) acc[a][b] = 0.f;
    float mr[4], lr_[4];
#pragma unroll
    for (int a = 0; a < 4; a++) { mr[a] = -INFINITY; lr_[a] = 0.f; }

    const float cs = 0.04419417382415922f * 1.4426950408889634f; // 1/sqrt(512)*log2(e)

    for (int kt = 0; kt < SS / 64; kt++) {
        const float* Kb = Kbase + kt * 64 * DD;
        const float* Vb = Vbase + kt * 64 * DD;

        __syncthreads();   // previous iter done reading Ks/Vs (+Q store visible)

        // K tile transposed w/ swizzle (conflict-free STS)
        {
            int r = t >> 2, cb = (t & 3) * 16;
            const float* kp = Kb + r * 64 + cb;
#pragma unroll
            for (int xk = 0; xk < 4; xk++) {
                float4 v = *(const float4*)(kp + 4 * xk);
                int c  = cb + 4 * xk;
                int rs = r ^ (((c >> 4) & 3) << 3);
                Ks[c + 0][rs] = v.x; Ks[c + 1][rs] = v.y;
                Ks[c + 2][rs] = v.z; Ks[c + 3][rs] = v.w;
            }
        }
        // V tile natural, flat coalesced copy
        {
            float*       vd = &Vs[0][0];
#pragma unroll
            for (int p = 0; p < 4; p++)
                *(float4*)(vd + p * 1024 + t * 4) =
                    *(const float4*)(Vb + p * 1024 + t * 4);
        }
        __syncthreads();

        // ---- GEMM1: s = Q @ K^T (4x4 per thread) ----
        float s[4][4];
#pragma unroll
        for (int a = 0; a < 4; a++)
#pragma unroll
            for (int b = 0; b < 4; b++) s[a][b] = 0.f;

#pragma unroll
        for (int ko = 0; ko < 4; ko++) {
            int sw = ko << 3;
            int ma = m0 ^ sw, na = n0 ^ sw;
#pragma unroll
            for (int kk = 0; kk < 16; kk++) {
                int k = ko * 16 + kk;
                float4 a = *(const float4*)(&Qs[k][ma]);
                float4 b = *(const float4*)(&Ks[k][na]);
                s[0][0] += a.x * b.x; s[0][1] += a.x * b.y;
                s[0][2] += a.x * b.z; s[0][3] += a.x * b.w;
                s[1][0] += a.y * b.x; s[1][1] += a.y * b.y;
                s[1][2] += a.y * b.z; s[1][3] += a.y * b.w;
                s[2][0] += a.z * b.x; s[2][1] += a.z * b.y;
                s[2][2] += a.z * b.z; s[2][3] += a.z * b.w;
                s[3][0] += a.w * b.x; s[3][1] += a.w * b.y;
                s[3][2] += a.w * b.z; s[3][3] += a.w * b.w;
            }
        }

        // ---- online softmax (rows owned by 16-lane groups) ----
#pragma unroll
        for (int mi = 0; mi < 4; mi++) {
            float mx = fmaxf(fmaxf(s[mi][0], s[mi][1]),
                             fmaxf(s[mi][2], s[mi][3]));
            mx = fmaxf(mx, __shfl_xor_sync(0xffffffffu, mx, 1, 16));
            mx = fmaxf(mx, __shfl_xor_sync(0xffffffffu, mx, 2, 16));
            mx = fmaxf(mx, __shfl_xor_sync(0xffffffffu, mx, 4, 16));
            mx = fmaxf(mx, __shfl_xor_sync(0xffffffffu, mx, 8, 16));
            float mnew = fmaxf(mr[mi], mx);
            float al   = exp2f((mr[mi] - mnew) * cs);
            mr[mi] = mnew;
            float ssum = 0.f;
#pragma unroll
            for (int ni = 0; ni < 4; ni++) {
                s[mi][ni] = exp2f((s[mi][ni] - mnew) * cs);
                ssum += s[mi][ni];
            }
            ssum += __shfl_xor_sync(0xffffffffu, ssum, 1, 16);
            ssum += __shfl_xor_sync(0xffffffffu, ssum, 2, 16);
            ssum += __shfl_xor_sync(0xffffffffu, ssum, 4, 16);
            ssum += __shfl_xor_sync(0xffffffffu, ssum, 8, 16);
            lr_[mi] = lr_[mi] * al + ssum;
            acc[mi][0] *= al; acc[mi][1] *= al;
            acc[mi][2] *= al; acc[mi][3] *= al;
        }

        // ---- GEMM2: acc += P @ V  (P broadcast via width-16 shfl) ----
        for (int jo = 0; jo < 16; jo++) {
#pragma unroll
            for (int nn = 0; nn < 4; nn++) {
                int n = jo * 4 + nn;
                float4 b = *(const float4*)(&Vs[n][n0]);
                float p0 = __shfl_sync(0xffffffffu, s[0][nn], jo, 16);
                float p1 = __shfl_sync(0xffffffffu, s[1][nn], jo, 16);
                float p2 = __shfl_sync(0xffffffffu, s[2][nn], jo, 16);
                float p3 = __shfl_sync(0xffffffffu, s[3][nn], jo, 16);
                acc[0][0] += p0 * b.x; acc[0][1] += p0 * b.y;
                acc[0][2] += p0 * b.z; acc[0][3] += p0 * b.w;
                acc[1][0] += p1 * b.x; acc[1][1] += p1 * b.y;
                acc[1][2] += p1 * b.z; acc[1][3] += p1 * b.w;
                acc[2][0] += p2 * b.x; acc[2][1] += p2 * b.y;
                acc[2][2] += p2 * b.z; acc[2][3] += p2 * b.w;
                acc[3][0] += p3 * b.x; acc[3][1] += p3 * b.y;
                acc[3][2] += p3 * b.z; acc[3][3] += p3 * b.w;
            }
        }
    }

    // ---- epilogue: normalize + write [B,S,E] ----
    int b = bh >> 3, h = bh & 7;
#pragma unroll
    for (int mi = 0; mi < 4; mi++) {
        float inv = 1.f / lr_[mi];
        float4 o4;
        o4.x = acc[mi][0] * inv; o4.y = acc[mi][1] * inv;
        o4.z = acc[mi][2] * inv; o4.w = acc[mi][3] * inv;
        *(float4*)(g_o + ((b * SS + q0 + m0 + mi) * EE) + h * 64 + n0) = o4;
    }
}

// ---------------------------------------------------------------------------
// Kernel 3: output projection  out = X @ Wo^T + bo   (KT=32)
// ---------------------------------------------------------------------------
__global__ void __launch_bounds__(256) out_gemm_kernel(
    const float* __restrict__ Wo, const float* __restrict__ bo,
    float* __restrict__ out)
{
    __shared__ float As[32][64];
    __shared__ float Bs[32][64];

    int t  = threadIdx.x;
    int m0 = blockIdx.x * 64;
    int n0 = blockIdx.y * 64;
    int tm = (t >> 4) * 4;
    int tn = (t & 15) * 4;

    float acc[4][4];
#pragma unroll
    for (int i = 0; i < 4; i++)
#pragma unroll
        for (int j = 0; j < 4; j++) acc[i][j] = 0.f;

    const float* X = g_o;
    int lr = t >> 2;           // 0..63
    int lc = (t & 3) * 4;      // 0,4,8,12

    for (int k0 = 0; k0 < 512; k0 += 32) {
        __syncthreads();
#pragma unroll
        for (int hh = 0; hh < 2; hh++) {
            int kk = lc + 16 * hh;
            float4 a = *(const float4*)(X  + (m0 + lr) * 512 + k0 + kk);
            float4 b = *(const float4*)(Wo + (n0 + lr) * 512 + k0 + kk);
            As[kk + 0][lr] = a.x; As[kk + 1][lr] = a.y;
            As[kk + 2][lr] = a.z; As[kk + 3][lr] = a.w;
            Bs[kk + 0][lr] = b.x; Bs[kk + 1][lr] = b.y;
            Bs[kk + 2][lr] = b.z; Bs[kk + 3][lr] = b.w;
        }
        __syncthreads();

#pragma unroll
        for (int k = 0; k < 32; k++) {
            float4 ar = *(const float4*)(&As[k][tm]);
            float4 br = *(const float4*)(&Bs[k][tn]);
            acc[0][0] += ar.x * br.x; acc[0][1] += ar.x * br.y;
            acc[0][2] += ar.x * br.z; acc[0][3] += ar.x * br.w;
            acc[1][0] += ar.y * br.x; acc[1][1] += ar.y * br.y;
            acc[1][2] += ar.y * br.z; acc[1][3] += ar.y * br.w;
            acc[2][0] += ar.z * br.x; acc[2][1] += ar.z * br.y;
            acc[2][2] += ar.z * br.z; acc[2][3] += ar.z * br.w;
            acc[3][0] += ar.w * br.x; acc[3][1] += ar.w * br.y;
            acc[3][2] += ar.w * br.z; acc[3][3] += ar.w * br.w;
        }
    }

#pragma unroll
    for (int i = 0; i < 4; i++) {
        float4 o4;
        o4.x = acc[i][0] + bo[n0 + tn + 0];
        o4.y = acc[i][1] + bo[n0 + tn + 1];
        o4.z = acc[i][2] + bo[n0 + tn + 2];
        o4.w = acc[i][3] + bo[n0 + tn + 3];
        *(float4*)(out + (m0 + tm + i) * 512 + n0 + tn) = o4;
    }
}

// ---------------------------------------------------------------------------
// Launch.  Input order: values, keys, query, Wv, Wk, Wq, Wo, bo
// ---------------------------------------------------------------------------
extern "C" void kernel_launch(void* const* d_in, const int* in_sizes, int n_in,
                              void* d_out, int out_size)
{
    const float* values = (const float*)d_in[0];
    const float* keys   = (const float*)d_in[1];
    const float* query  = (const float*)d_in[2];
    const float* Wv     = (const float*)d_in[3];
    const float* Wk     = (const float*)d_in[4];
    const float* Wq     = (const float*)d_in[5];
    const float* Wo     = (const float*)d_in[6];
    const float* bo     = (const float*)d_in[7];
    float* out = (float*)d_out;

    proj_kernel<<<1024, 256>>>(query,  Wq, 0);
    proj_kernel<<<1024, 256>>>(keys,   Wk, 1);
    proj_kernel<<<1024, 256>>>(values, Wv, 2);

    dim3 fgrid(SS / 64, BB * HH);
    flash2_kernel<<<fgrid, 256>>>();

    dim3 ggrid((BB * SS) / 64, EE / 64);
    out_gemm_kernel<<<ggrid, 256>>>(Wo, bo, out);
}

// round 3
// speedup vs baseline: 3.0493x; 2.1720x over previous
#include <cuda_runtime.h>
#include <math.h>
#include <stdint.h>

#define BB 4
#define SS 2048
#define EE 512
#define HH 8
#define DD 64

#define KSTR 68   // K tile SMEM row stride (floats) -> conflict-free B-frag LDS
#define VSTR 72   // V tile SMEM row stride

// Scratch (allocation-free requirement -> __device__ globals)
__device__ float g_qp[BB * HH * SS * DD];  // [B,H,S,D]
__device__ float g_kp[BB * HH * SS * DD];
__device__ float g_vp[BB * HH * SS * DD];
__device__ float g_o [BB * SS * EE];       // attention output, [B,S,E]

// ---------------------------------------------------------------------------
// helpers
// ---------------------------------------------------------------------------
__device__ __forceinline__ uint32_t f2tf(float f) {
    uint32_t u;
    asm("cvt.rna.tf32.f32 %0, %1;" : "=r"(u) : "f"(f));
    return u;
}

__device__ __forceinline__ void mma_tf32(float d[4], const uint32_t a[4],
                                         uint32_t b0, uint32_t b1) {
    asm volatile(
        "mma.sync.aligned.m16n8k8.row.col.f32.tf32.tf32.f32 "
        "{%0,%1,%2,%3}, {%4,%5,%6,%7}, {%8,%9}, {%0,%1,%2,%3};"
        : "+f"(d[0]), "+f"(d[1]), "+f"(d[2]), "+f"(d[3])
        : "r"(a[0]), "r"(a[1]), "r"(a[2]), "r"(a[3]), "r"(b0), "r"(b1));
}

// ---------------------------------------------------------------------------
// Kernel 1: per-head projection as a register-tiled GEMM (fp32).
// ---------------------------------------------------------------------------
__global__ void __launch_bounds__(256) proj_kernel(
    const float* __restrict__ x, const float* __restrict__ W, int which)
{
    float* out = (which == 0) ? g_qp : (which == 1) ? g_kp : g_vp;

    __shared__ float Xs[64][64];
    __shared__ float Wt[64][64];

    int t = threadIdx.x;
    int rbase = blockIdx.x * 64;

    {
        int r = t >> 2, cb = (t & 3) * 16;
        const float* xp = x + (rbase + r) * 64 + cb;
        const float* wp = W + r * 64 + cb;
#pragma unroll
        for (int xk = 0; xk < 4; xk++) {
            float4 v = *(const float4*)(xp + 4 * xk);
            int c = cb + 4 * xk;
            Xs[c + 0][r] = v.x; Xs[c + 1][r] = v.y;
            Xs[c + 2][r] = v.z; Xs[c + 3][r] = v.w;
            float4 w = *(const float4*)(wp + 4 * xk);
            Wt[c + 0][r] = w.x; Wt[c + 1][r] = w.y;
            Wt[c + 2][r] = w.z; Wt[c + 3][r] = w.w;
        }
    }
    __syncthreads();

    int tm = (t >> 4) * 4;
    int tn = (t & 15) * 4;

    float acc[4][4];
#pragma unroll
    for (int a = 0; a < 4; a++)
#pragma unroll
        for (int b = 0; b < 4; b++) acc[a][b] = 0.f;

#pragma unroll
    for (int k = 0; k < 64; k++) {
        float4 ar = *(const float4*)(&Xs[k][tm]);
        float4 br = *(const float4*)(&Wt[k][tn]);
        acc[0][0] += ar.x * br.x; acc[0][1] += ar.x * br.y;
        acc[0][2] += ar.x * br.z; acc[0][3] += ar.x * br.w;
        acc[1][0] += ar.y * br.x; acc[1][1] += ar.y * br.y;
        acc[1][2] += ar.y * br.z; acc[1][3] += ar.y * br.w;
        acc[2][0] += ar.z * br.x; acc[2][1] += ar.z * br.y;
        acc[2][2] += ar.z * br.z; acc[2][3] += ar.z * br.w;
        acc[3][0] += ar.w * br.x; acc[3][1] += ar.w * br.y;
        acc[3][2] += ar.w * br.z; acc[3][3] += ar.w * br.w;
    }

#pragma unroll
    for (int mi = 0; mi < 4; mi++) {
        int n   = rbase + tm + mi;
        int b   = n >> 14;
        int rem = n & 16383;
        int s   = rem >> 3;
        int h   = rem & 7;
        float4 o4;
        o4.x = acc[mi][0]; o4.y = acc[mi][1];
        o4.z = acc[mi][2]; o4.w = acc[mi][3];
        *(float4*)(out + (((b * HH + h) * SS) + s) * 64 + tn) = o4;
    }
}

// ---------------------------------------------------------------------------
// Kernel 2: flash attention on tensor cores (tf32 mma.sync m16n8k8).
// 4 warps/CTA, warp = 16 q rows, Bc = 64 kv per iteration.
// ---------------------------------------------------------------------------
__global__ void __launch_bounds__(128) flash3_kernel()
{
    __shared__ float Ks[64 * KSTR];   // [kv][d], tf32-rounded
    __shared__ float Vs[64 * VSTR];   // [kv][d], tf32-rounded

    int t  = threadIdx.x;
    int l  = t & 31;
    int w  = t >> 5;
    int bh = blockIdx.y;
    int q0 = blockIdx.x * 64;
    int r  = l >> 2;      // 0..7
    int c  = l & 3;       // 0..3

    const float* Kbase = g_kp + bh * SS * DD;
    const float* Vbase = g_vp + bh * SS * DD;

    // ---- Q fragments (register resident for whole kernel) ----
    uint32_t qf[8][4];
    {
        const float* Qb = g_qp + (bh * SS + q0 + w * 16) * 64;
#pragma unroll
        for (int kb = 0; kb < 8; kb++) {
            qf[kb][0] = f2tf(Qb[(r    ) * 64 + kb * 8 + c    ]);
            qf[kb][1] = f2tf(Qb[(r + 8) * 64 + kb * 8 + c    ]);
            qf[kb][2] = f2tf(Qb[(r    ) * 64 + kb * 8 + c + 4]);
            qf[kb][3] = f2tf(Qb[(r + 8) * 64 + kb * 8 + c + 4]);
        }
    }

    float o[8][4];
#pragma unroll
    for (int nb = 0; nb < 8; nb++)
#pragma unroll
        for (int j = 0; j < 4; j++) o[nb][j] = 0.f;
    float m0 = -INFINITY, m1 = -INFINITY, l0 = 0.f, l1 = 0.f;

    const float cs = 0.04419417382415922f * 1.4426950408889634f;

    int s0l = c >> 1;        // shfl src within quad (a0/a1)
    int s1l = s0l + 2;       // shfl src within quad (a2/a3)
    bool par = (c & 1);

    for (int kt = 0; kt < SS / 64; kt++) {
        __syncthreads();
        // ---- load K,V tile -> SMEM with tf32 rounding ----
        {
            const float4* Kg = (const float4*)(Kbase + kt * 64 * 64);
            const float4* Vg = (const float4*)(Vbase + kt * 64 * 64);
#pragma unroll
            for (int i = 0; i < 8; i++) {
                int idx = t + 128 * i;
                int row = idx >> 4, c4 = idx & 15;
                float4 kv = Kg[idx];
                float4 ko;
                ko.x = __uint_as_float(f2tf(kv.x));
                ko.y = __uint_as_float(f2tf(kv.y));
                ko.z = __uint_as_float(f2tf(kv.z));
                ko.w = __uint_as_float(f2tf(kv.w));
                *(float4*)(&Ks[row * KSTR + c4 * 4]) = ko;
                float4 vv = Vg[idx];
                float4 vo;
                vo.x = __uint_as_float(f2tf(vv.x));
                vo.y = __uint_as_float(f2tf(vv.y));
                vo.z = __uint_as_float(f2tf(vv.z));
                vo.w = __uint_as_float(f2tf(vv.w));
                *(float4*)(&Vs[row * VSTR + c4 * 4]) = vo;
            }
        }
        __syncthreads();

        // ---- GEMM1: S = Q @ K^T ----
        float s[8][4];
#pragma unroll
        for (int nb = 0; nb < 8; nb++)
#pragma unroll
            for (int j = 0; j < 4; j++) s[nb][j] = 0.f;

#pragma unroll
        for (int kb = 0; kb < 8; kb++) {
#pragma unroll
            for (int nb = 0; nb < 8; nb++) {
                uint32_t b0 = __float_as_uint(Ks[(nb * 8 + r) * KSTR + kb * 8 + c    ]);
                uint32_t b1 = __float_as_uint(Ks[(nb * 8 + r) * KSTR + kb * 8 + c + 4]);
                mma_tf32(s[nb], qf[kb], b0, b1);
            }
        }

        // ---- online softmax (rows r and r+8, quad-reduced) ----
        float mx0 = -INFINITY, mx1 = -INFINITY;
#pragma unroll
        for (int nb = 0; nb < 8; nb++) {
            mx0 = fmaxf(mx0, fmaxf(s[nb][0], s[nb][1]));
            mx1 = fmaxf(mx1, fmaxf(s[nb][2], s[nb][3]));
        }
        mx0 = fmaxf(mx0, __shfl_xor_sync(0xffffffffu, mx0, 1, 4));
        mx0 = fmaxf(mx0, __shfl_xor_sync(0xffffffffu, mx0, 2, 4));
        mx1 = fmaxf(mx1, __shfl_xor_sync(0xffffffffu, mx1, 1, 4));
        mx1 = fmaxf(mx1, __shfl_xor_sync(0xffffffffu, mx1, 2, 4));

        float mn0 = fmaxf(m0, mx0), mn1 = fmaxf(m1, mx1);
        float al0 = exp2f((m0 - mn0) * cs), al1 = exp2f((m1 - mn1) * cs);
        m0 = mn0; m1 = mn1;

        float sum0 = 0.f, sum1 = 0.f;
#pragma unroll
        for (int nb = 0; nb < 8; nb++) {
            s[nb][0] = exp2f((s[nb][0] - mn0) * cs);
            s[nb][1] = exp2f((s[nb][1] - mn0) * cs);
            s[nb][2] = exp2f((s[nb][2] - mn1) * cs);
            s[nb][3] = exp2f((s[nb][3] - mn1) * cs);
            sum0 += s[nb][0] + s[nb][1];
            sum1 += s[nb][2] + s[nb][3];
        }
        sum0 += __shfl_xor_sync(0xffffffffu, sum0, 1, 4);
        sum0 += __shfl_xor_sync(0xffffffffu, sum0, 2, 4);
        sum1 += __shfl_xor_sync(0xffffffffu, sum1, 1, 4);
        sum1 += __shfl_xor_sync(0xffffffffu, sum1, 2, 4);
        l0 = l0 * al0 + sum0;
        l1 = l1 * al1 + sum1;

#pragma unroll
        for (int nb = 0; nb < 8; nb++) {
            o[nb][0] *= al0; o[nb][1] *= al0;
            o[nb][2] *= al1; o[nb][3] *= al1;
        }

        // ---- P: C-fragment -> A-fragment relayout (width-4 shfls) ----
        uint32_t pa[8][4];
#pragma unroll
        for (int nb = 0; nb < 8; nb++) {
            uint32_t p0 = f2tf(s[nb][0]);
            uint32_t p1 = f2tf(s[nb][1]);
            uint32_t p2 = f2tf(s[nb][2]);
            uint32_t p3 = f2tf(s[nb][3]);
            uint32_t u0 = __shfl_sync(0xffffffffu, p0, s0l, 4);
            uint32_t u1 = __shfl_sync(0xffffffffu, p1, s0l, 4);
            pa[nb][0] = par ? u1 : u0;
            uint32_t v0 = __shfl_sync(0xffffffffu, p2, s0l, 4);
            uint32_t v1 = __shfl_sync(0xffffffffu, p3, s0l, 4);
            pa[nb][1] = par ? v1 : v0;
            uint32_t w0 = __shfl_sync(0xffffffffu, p0, s1l, 4);
            uint32_t w1 = __shfl_sync(0xffffffffu, p1, s1l, 4);
            pa[nb][2] = par ? w1 : w0;
            uint32_t x0 = __shfl_sync(0xffffffffu, p2, s1l, 4);
            uint32_t x1 = __shfl_sync(0xffffffffu, p3, s1l, 4);
            pa[nb][3] = par ? x1 : x0;
        }

        // ---- GEMM2: O += P @ V ----
#pragma unroll
        for (int kb = 0; kb < 8; kb++) {
#pragma unroll
            for (int nb = 0; nb < 8; nb++) {
                uint32_t b0 = __float_as_uint(Vs[(kb * 8 + c    ) * VSTR + nb * 8 + r]);
                uint32_t b1 = __float_as_uint(Vs[(kb * 8 + c + 4) * VSTR + nb * 8 + r]);
                mma_tf32(o[nb], pa[kb], b0, b1);
            }
        }
    }

    // ---- epilogue: normalize + write [B,S,E] ----
    float inv0 = 1.f / l0, inv1 = 1.f / l1;
    int b = bh >> 3, h = bh & 7;
    int row0 = q0 + w * 16 + r;
    float* O0 = g_o + ((size_t)(b * SS + row0    )) * EE + h * 64;
    float* O1 = g_o + ((size_t)(b * SS + row0 + 8)) * EE + h * 64;
#pragma unroll
    for (int nb = 0; nb < 8; nb++) {
        float2 lo; lo.x = o[nb][0] * inv0; lo.y = o[nb][1] * inv0;
        float2 hi; hi.x = o[nb][2] * inv1; hi.y = o[nb][3] * inv1;
        *(float2*)(O0 + nb * 8 + 2 * c) = lo;
        *(float2*)(O1 + nb * 8 + 2 * c) = hi;
    }
}

// ---------------------------------------------------------------------------
// Kernel 3: output projection  out = X @ Wo^T + bo   (fp32, KT=32)
// ---------------------------------------------------------------------------
__global__ void __launch_bounds__(256) out_gemm_kernel(
    const float* __restrict__ Wo, const float* __restrict__ bo,
    float* __restrict__ out)
{
    __shared__ float As[32][64];
    __shared__ float Bs[32][64];

    int t  = threadIdx.x;
    int m0 = blockIdx.x * 64;
    int n0 = blockIdx.y * 64;
    int tm = (t >> 4) * 4;
    int tn = (t & 15) * 4;

    float acc[4][4];
#pragma unroll
    for (int i = 0; i < 4; i++)
#pragma unroll
        for (int j = 0; j < 4; j++) acc[i][j] = 0.f;

    const float* X = g_o;
    int lr = t >> 2;
    int lc = (t & 3) * 4;

    for (int k0 = 0; k0 < 512; k0 += 32) {
        __syncthreads();
#pragma unroll
        for (int hh = 0; hh < 2; hh++) {
            int kk = lc + 16 * hh;
            float4 a = *(const float4*)(X  + (m0 + lr) * 512 + k0 + kk);
            float4 b = *(const float4*)(Wo + (n0 + lr) * 512 + k0 + kk);
            As[kk + 0][lr] = a.x; As[kk + 1][lr] = a.y;
            As[kk + 2][lr] = a.z; As[kk + 3][lr] = a.w;
            Bs[kk + 0][lr] = b.x; Bs[kk + 1][lr] = b.y;
            Bs[kk + 2][lr] = b.z; Bs[kk + 3][lr] = b.w;
        }
        __syncthreads();

#pragma unroll
        for (int k = 0; k < 32; k++) {
            float4 ar = *(const float4*)(&As[k][tm]);
            float4 br = *(const float4*)(&Bs[k][tn]);
            acc[0][0] += ar.x * br.x; acc[0][1] += ar.x * br.y;
            acc[0][2] += ar.x * br.z; acc[0][3] += ar.x * br.w;
            acc[1][0] += ar.y * br.x; acc[1][1] += ar.y * br.y;
            acc[1][2] += ar.y * br.z; acc[1][3] += ar.y * br.w;
            acc[2][0] += ar.z * br.x; acc[2][1] += ar.z * br.y;
            acc[2][2] += ar.z * br.z; acc[2][3] += ar.z * br.w;
            acc[3][0] += ar.w * br.x; acc[3][1] += ar.w * br.y;
            acc[3][2] += ar.w * br.z; acc[3][3] += ar.w * br.w;
        }
    }

#pragma unroll
    for (int i = 0; i < 4; i++) {
        float4 o4;
        o4.x = acc[i][0] + bo[n0 + tn + 0];
        o4.y = acc[i][1] + bo[n0 + tn + 1];
        o4.z = acc[i][2] + bo[n0 + tn + 2];
        o4.w = acc[i][3] + bo[n0 + tn + 3];
        *(float4*)(out + (m0 + tm + i) * 512 + n0 + tn) = o4;
    }
}

// ---------------------------------------------------------------------------
// Launch.  Input order: values, keys, query, Wv, Wk, Wq, Wo, bo
// ---------------------------------------------------------------------------
extern "C" void kernel_launch(void* const* d_in, const int* in_sizes, int n_in,
                              void* d_out, int out_size)
{
    const float* values = (const float*)d_in[0];
    const float* keys   = (const float*)d_in[1];
    const float* query  = (const float*)d_in[2];
    const float* Wv     = (const float*)d_in[3];
    const float* Wk     = (const float*)d_in[4];
    const float* Wq     = (const float*)d_in[5];
    const float* Wo     = (const float*)d_in[6];
    const float* bo     = (const float*)d_in[7];
    float* out = (float*)d_out;

    proj_kernel<<<1024, 256>>>(query,  Wq, 0);
    proj_kernel<<<1024, 256>>>(keys,   Wk, 1);
    proj_kernel<<<1024, 256>>>(values, Wv, 2);

    dim3 fgrid(SS / 64, BB * HH);
    flash3_kernel<<<fgrid, 128>>>();

    dim3 ggrid((BB * SS) / 64, EE / 64);
    out_gemm_kernel<<<ggrid, 256>>>(Wo, bo, out);
}

// round 4
// speedup vs baseline: 4.4914x; 1.4730x over previous
#include <cuda_runtime.h>
#include <math.h>
#include <stdint.h>

#define BB 4
#define SS 2048
#define EE 512
#define HH 8
#define DD 64

#define KSTR 68   // K tile SMEM row stride (floats) -> conflict-free B-frag LDS
#define VSTR 72   // V tile SMEM row stride
#define KTILE (64 * KSTR)
#define VTILE (64 * VSTR)

// Scratch (allocation-free requirement -> __device__ globals)
__device__ float g_qp[BB * HH * SS * DD];  // [B,H,S,D]  (tf32-pre-rounded)
__device__ float g_kp[BB * HH * SS * DD];
__device__ float g_vp[BB * HH * SS * DD];
__device__ float g_o [BB * SS * EE];       // attention output, [B,S,E] fp32

// ---------------------------------------------------------------------------
// helpers
// ---------------------------------------------------------------------------
__device__ __forceinline__ uint32_t f2tf(float f) {
    uint32_t u;
    asm("cvt.rna.tf32.f32 %0, %1;" : "=r"(u) : "f"(f));
    return u;
}

__device__ __forceinline__ void mma_tf32(float d[4], const uint32_t a[4],
                                         uint32_t b0, uint32_t b1) {
    asm volatile(
        "mma.sync.aligned.m16n8k8.row.col.f32.tf32.tf32.f32 "
        "{%0,%1,%2,%3}, {%4,%5,%6,%7}, {%8,%9}, {%0,%1,%2,%3};"
        : "+f"(d[0]), "+f"(d[1]), "+f"(d[2]), "+f"(d[3])
        : "r"(a[0]), "r"(a[1]), "r"(a[2]), "r"(a[3]), "r"(b0), "r"(b1));
}

__device__ __forceinline__ void cp16(float* smem_dst, const float* gsrc) {
    uint32_t s = (uint32_t)__cvta_generic_to_shared(smem_dst);
    asm volatile("cp.async.cg.shared.global [%0], [%1], 16;" :: "r"(s), "l"(gsrc));
}

// ---------------------------------------------------------------------------
// Kernel 1: per-head projection, fp32 GEMM, output tf32-pre-rounded.
// ---------------------------------------------------------------------------
__global__ void __launch_bounds__(256) proj_kernel(
    const float* __restrict__ x, const float* __restrict__ W, int which)
{
    float* out = (which == 0) ? g_qp : (which == 1) ? g_kp : g_vp;

    __shared__ float Xs[64][64];
    __shared__ float Wt[64][64];

    int t = threadIdx.x;
    int rbase = blockIdx.x * 64;

    {
        int r = t >> 2, cb = (t & 3) * 16;
        const float* xp = x + (rbase + r) * 64 + cb;
        const float* wp = W + r * 64 + cb;
#pragma unroll
        for (int xk = 0; xk < 4; xk++) {
            float4 v = *(const float4*)(xp + 4 * xk);
            int c = cb + 4 * xk;
            Xs[c + 0][r] = v.x; Xs[c + 1][r] = v.y;
            Xs[c + 2][r] = v.z; Xs[c + 3][r] = v.w;
            float4 w = *(const float4*)(wp + 4 * xk);
            Wt[c + 0][r] = w.x; Wt[c + 1][r] = w.y;
            Wt[c + 2][r] = w.z; Wt[c + 3][r] = w.w;
        }
    }
    __syncthreads();

    int tm = (t >> 4) * 4;
    int tn = (t & 15) * 4;

    float acc[4][4];
#pragma unroll
    for (int a = 0; a < 4; a++)
#pragma unroll
        for (int b = 0; b < 4; b++) acc[a][b] = 0.f;

#pragma unroll
    for (int k = 0; k < 64; k++) {
        float4 ar = *(const float4*)(&Xs[k][tm]);
        float4 br = *(const float4*)(&Wt[k][tn]);
        acc[0][0] += ar.x * br.x; acc[0][1] += ar.x * br.y;
        acc[0][2] += ar.x * br.z; acc[0][3] += ar.x * br.w;
        acc[1][0] += ar.y * br.x; acc[1][1] += ar.y * br.y;
        acc[1][2] += ar.y * br.z; acc[1][3] += ar.y * br.w;
        acc[2][0] += ar.z * br.x; acc[2][1] += ar.z * br.y;
        acc[2][2] += ar.z * br.z; acc[2][3] += ar.z * br.w;
        acc[3][0] += ar.w * br.x; acc[3][1] += ar.w * br.y;
        acc[3][2] += ar.w * br.z; acc[3][3] += ar.w * br.w;
    }

#pragma unroll
    for (int mi = 0; mi < 4; mi++) {
        int n   = rbase + tm + mi;
        int b   = n >> 14;
        int rem = n & 16383;
        int s   = rem >> 3;
        int h   = rem & 7;
        float4 o4;
        o4.x = __uint_as_float(f2tf(acc[mi][0]));
        o4.y = __uint_as_float(f2tf(acc[mi][1]));
        o4.z = __uint_as_float(f2tf(acc[mi][2]));
        o4.w = __uint_as_float(f2tf(acc[mi][3]));
        *(float4*)(out + (((b * HH + h) * SS) + s) * 64 + tn) = o4;
    }
}

// ---------------------------------------------------------------------------
// Kernel 2: flash attention on tensor cores, cp.async double-buffered K/V.
// 4 warps/CTA, warp = 16 q rows, Bc = 64.  Dynamic SMEM = 2*(KTILE+VTILE)*4B.
// ---------------------------------------------------------------------------
__global__ void __launch_bounds__(128) flash4_kernel()
{
    extern __shared__ float dsm[];
    float* KsBuf = dsm;                  // [2][KTILE]
    float* VsBuf = dsm + 2 * KTILE;      // [2][VTILE]

    int t  = threadIdx.x;
    int l  = t & 31;
    int w  = t >> 5;
    int bh = blockIdx.y;
    int q0 = blockIdx.x * 64;
    int r  = l >> 2;
    int c  = l & 3;

    const float* Kbase = g_kp + bh * SS * DD;
    const float* Vbase = g_vp + bh * SS * DD;

    // ---- Q fragments (pre-rounded tf32 in gmem) ----
    uint32_t qf[8][4];
    {
        const float* Qb = g_qp + (bh * SS + q0 + w * 16) * 64;
#pragma unroll
        for (int kb = 0; kb < 8; kb++) {
            qf[kb][0] = __float_as_uint(Qb[(r    ) * 64 + kb * 8 + c    ]);
            qf[kb][1] = __float_as_uint(Qb[(r + 8) * 64 + kb * 8 + c    ]);
            qf[kb][2] = __float_as_uint(Qb[(r    ) * 64 + kb * 8 + c + 4]);
            qf[kb][3] = __float_as_uint(Qb[(r + 8) * 64 + kb * 8 + c + 4]);
        }
    }

    float o[8][4];
#pragma unroll
    for (int nb = 0; nb < 8; nb++)
#pragma unroll
        for (int j = 0; j < 4; j++) o[nb][j] = 0.f;
    float m0 = -INFINITY, m1 = -INFINITY, l0 = 0.f, l1 = 0.f;

    const float cs = 0.04419417382415922f * 1.4426950408889634f;

    int s0l = c >> 1;
    int s1l = s0l + 2;
    bool par = (c & 1);

    // prologue: async-load tile 0
    {
        const float4* Kg = (const float4*)(Kbase);
        const float4* Vg = (const float4*)(Vbase);
#pragma unroll
        for (int i = 0; i < 8; i++) {
            int idx = t + 128 * i;
            int row = idx >> 4, c4 = idx & 15;
            cp16(&KsBuf[row * KSTR + c4 * 4], (const float*)(Kg + idx));
            cp16(&VsBuf[row * VSTR + c4 * 4], (const float*)(Vg + idx));
        }
        asm volatile("cp.async.commit_group;");
    }

    for (int kt = 0; kt < SS / 64; kt++) {
        // issue next tile into the other buffer
        if (kt + 1 < SS / 64) {
            int nb_ = (kt + 1) & 1;
            const float4* Kg = (const float4*)(Kbase + (kt + 1) * 64 * 64);
            const float4* Vg = (const float4*)(Vbase + (kt + 1) * 64 * 64);
            float* Kd = KsBuf + nb_ * KTILE;
            float* Vd = VsBuf + nb_ * VTILE;
#pragma unroll
            for (int i = 0; i < 8; i++) {
                int idx = t + 128 * i;
                int row = idx >> 4, c4 = idx & 15;
                cp16(&Kd[row * KSTR + c4 * 4], (const float*)(Kg + idx));
                cp16(&Vd[row * VSTR + c4 * 4], (const float*)(Vg + idx));
            }
            asm volatile("cp.async.commit_group;");
            asm volatile("cp.async.wait_group 1;");
        } else {
            asm volatile("cp.async.wait_group 0;");
        }
        __syncthreads();

        const float* Ks = KsBuf + (kt & 1) * KTILE;
        const float* Vs = VsBuf + (kt & 1) * VTILE;

        // ---- GEMM1: S = Q @ K^T ----
        float s[8][4];
#pragma unroll
        for (int nb = 0; nb < 8; nb++)
#pragma unroll
            for (int j = 0; j < 4; j++) s[nb][j] = 0.f;

#pragma unroll
        for (int kb = 0; kb < 8; kb++) {
#pragma unroll
            for (int nb = 0; nb < 8; nb++) {
                uint32_t b0 = __float_as_uint(Ks[(nb * 8 + r) * KSTR + kb * 8 + c    ]);
                uint32_t b1 = __float_as_uint(Ks[(nb * 8 + r) * KSTR + kb * 8 + c + 4]);
                mma_tf32(s[nb], qf[kb], b0, b1);
            }
        }

        // ---- online softmax ----
        float mx0 = -INFINITY, mx1 = -INFINITY;
#pragma unroll
        for (int nb = 0; nb < 8; nb++) {
            mx0 = fmaxf(mx0, fmaxf(s[nb][0], s[nb][1]));
            mx1 = fmaxf(mx1, fmaxf(s[nb][2], s[nb][3]));
        }
        mx0 = fmaxf(mx0, __shfl_xor_sync(0xffffffffu, mx0, 1, 4));
        mx0 = fmaxf(mx0, __shfl_xor_sync(0xffffffffu, mx0, 2, 4));
        mx1 = fmaxf(mx1, __shfl_xor_sync(0xffffffffu, mx1, 1, 4));
        mx1 = fmaxf(mx1, __shfl_xor_sync(0xffffffffu, mx1, 2, 4));

        float mn0 = fmaxf(m0, mx0), mn1 = fmaxf(m1, mx1);
        float al0 = exp2f((m0 - mn0) * cs), al1 = exp2f((m1 - mn1) * cs);
        m0 = mn0; m1 = mn1;

        float sum0 = 0.f, sum1 = 0.f;
#pragma unroll
        for (int nb = 0; nb < 8; nb++) {
            s[nb][0] = exp2f((s[nb][0] - mn0) * cs);
            s[nb][1] = exp2f((s[nb][1] - mn0) * cs);
            s[nb][2] = exp2f((s[nb][2] - mn1) * cs);
            s[nb][3] = exp2f((s[nb][3] - mn1) * cs);
            sum0 += s[nb][0] + s[nb][1];
            sum1 += s[nb][2] + s[nb][3];
        }
        sum0 += __shfl_xor_sync(0xffffffffu, sum0, 1, 4);
        sum0 += __shfl_xor_sync(0xffffffffu, sum0, 2, 4);
        sum1 += __shfl_xor_sync(0xffffffffu, sum1, 1, 4);
        sum1 += __shfl_xor_sync(0xffffffffu, sum1, 2, 4);
        l0 = l0 * al0 + sum0;
        l1 = l1 * al1 + sum1;

#pragma unroll
        for (int nb = 0; nb < 8; nb++) {
            o[nb][0] *= al0; o[nb][1] *= al0;
            o[nb][2] *= al1; o[nb][3] *= al1;
        }

        // ---- P: C-fragment -> A-fragment relayout ----
        uint32_t pa[8][4];
#pragma unroll
        for (int nb = 0; nb < 8; nb++) {
            uint32_t p0 = f2tf(s[nb][0]);
            uint32_t p1 = f2tf(s[nb][1]);
            uint32_t p2 = f2tf(s[nb][2]);
            uint32_t p3 = f2tf(s[nb][3]);
            uint32_t u0 = __shfl_sync(0xffffffffu, p0, s0l, 4);
            uint32_t u1 = __shfl_sync(0xffffffffu, p1, s0l, 4);
            pa[nb][0] = par ? u1 : u0;
            uint32_t v0 = __shfl_sync(0xffffffffu, p2, s0l, 4);
            uint32_t v1 = __shfl_sync(0xffffffffu, p3, s0l, 4);
            pa[nb][1] = par ? v1 : v0;
            uint32_t w0 = __shfl_sync(0xffffffffu, p0, s1l, 4);
            uint32_t w1 = __shfl_sync(0xffffffffu, p1, s1l, 4);
            pa[nb][2] = par ? w1 : w0;
            uint32_t x0 = __shfl_sync(0xffffffffu, p2, s1l, 4);
            uint32_t x1 = __shfl_sync(0xffffffffu, p3, s1l, 4);
            pa[nb][3] = par ? x1 : x0;
        }

        // ---- GEMM2: O += P @ V ----
#pragma unroll
        for (int kb = 0; kb < 8; kb++) {
#pragma unroll
            for (int nb = 0; nb < 8; nb++) {
                uint32_t b0 = __float_as_uint(Vs[(kb * 8 + c    ) * VSTR + nb * 8 + r]);
                uint32_t b1 = __float_as_uint(Vs[(kb * 8 + c + 4) * VSTR + nb * 8 + r]);
                mma_tf32(o[nb], pa[kb], b0, b1);
            }
        }
        __syncthreads();
    }

    // ---- epilogue ----
    float inv0 = 1.f / l0, inv1 = 1.f / l1;
    int b = bh >> 3, h = bh & 7;
    int row0 = q0 + w * 16 + r;
    float* O0 = g_o + ((size_t)(b * SS + row0    )) * EE + h * 64;
    float* O1 = g_o + ((size_t)(b * SS + row0 + 8)) * EE + h * 64;
#pragma unroll
    for (int nb = 0; nb < 8; nb++) {
        float2 lo; lo.x = o[nb][0] * inv0; lo.y = o[nb][1] * inv0;
        float2 hi; hi.x = o[nb][2] * inv1; hi.y = o[nb][3] * inv1;
        *(float2*)(O0 + nb * 8 + 2 * c) = lo;
        *(float2*)(O1 + nb * 8 + 2 * c) = hi;
    }
}

// ---------------------------------------------------------------------------
// Kernel 3: output projection on tensor cores (tf32).
// CTA: 256 thr, tile 128(m) x 128(n), warp tile 32x64. out = X @ Wo^T + bo.
// ---------------------------------------------------------------------------
#define OSTR 36

__global__ void __launch_bounds__(256) out_gemm_tc(
    const float* __restrict__ Wo, const float* __restrict__ bo,
    float* __restrict__ out)
{
    __shared__ float As[128][OSTR];
    __shared__ float Bs[128][OSTR];

    int t  = threadIdx.x;
    int l  = t & 31;
    int w  = t >> 5;
    int r  = l >> 2;
    int c  = l & 3;
    int wm = (w & 3) * 32;    // m strip
    int wn = (w >> 2) * 64;   // n strip
    int m0 = blockIdx.x * 128;
    int n0 = blockIdx.y * 128;

    const float* X = g_o;

    float acc[2][8][4];
#pragma unroll
    for (int mi = 0; mi < 2; mi++)
#pragma unroll
        for (int nb = 0; nb < 8; nb++)
#pragma unroll
            for (int j = 0; j < 4; j++) acc[mi][nb][j] = 0.f;

    for (int k0 = 0; k0 < 512; k0 += 32) {
        __syncthreads();
#pragma unroll
        for (int i = 0; i < 4; i++) {
            int flat = t + 256 * i;      // 0..1023
            int row = flat >> 3, c4 = (flat & 7) * 4;
            float4 a = *(const float4*)(X  + (m0 + row) * 512 + k0 + c4);
            float4 b = *(const float4*)(Wo + (n0 + row) * 512 + k0 + c4);
            float4 ar, br;
            ar.x = __uint_as_float(f2tf(a.x)); ar.y = __uint_as_float(f2tf(a.y));
            ar.z = __uint_as_float(f2tf(a.z)); ar.w = __uint_as_float(f2tf(a.w));
            br.x = __uint_as_float(f2tf(b.x)); br.y = __uint_as_float(f2tf(b.y));
            br.z = __uint_as_float(f2tf(b.z)); br.w = __uint_as_float(f2tf(b.w));
            *(float4*)(&As[row][c4]) = ar;
            *(float4*)(&Bs[row][c4]) = br;
        }
        __syncthreads();

#pragma unroll
        for (int k8 = 0; k8 < 4; k8++) {
            int kk = k8 * 8;
            uint32_t af[2][4];
#pragma unroll
            for (int mi = 0; mi < 2; mi++) {
                int row = wm + mi * 16;
                af[mi][0] = __float_as_uint(As[row + r    ][kk + c    ]);
                af[mi][1] = __float_as_uint(As[row + r + 8][kk + c    ]);
                af[mi][2] = __float_as_uint(As[row + r    ][kk + c + 4]);
                af[mi][3] = __float_as_uint(As[row + r + 8][kk + c + 4]);
            }
#pragma unroll
            for (int nb = 0; nb < 8; nb++) {
                uint32_t b0 = __float_as_uint(Bs[wn + nb * 8 + r][kk + c    ]);
                uint32_t b1 = __float_as_uint(Bs[wn + nb * 8 + r][kk + c + 4]);
                mma_tf32(acc[0][nb], af[0], b0, b1);
                mma_tf32(acc[1][nb], af[1], b0, b1);
            }
        }
    }

    // epilogue
#pragma unroll
    for (int mi = 0; mi < 2; mi++) {
        int row = m0 + wm + mi * 16 + r;
#pragma unroll
        for (int nb = 0; nb < 8; nb++) {
            int col = n0 + wn + nb * 8 + 2 * c;
            float b0 = bo[col], b1 = bo[col + 1];
            float2 lo; lo.x = acc[mi][nb][0] + b0; lo.y = acc[mi][nb][1] + b1;
            float2 hi; hi.x = acc[mi][nb][2] + b0; hi.y = acc[mi][nb][3] + b1;
            *(float2*)(out + (size_t)row * 512 + col)        = lo;
            *(float2*)(out + (size_t)(row + 8) * 512 + col)  = hi;
        }
    }
}

// ---------------------------------------------------------------------------
// Launch.  Input order: values, keys, query, Wv, Wk, Wq, Wo, bo
// ---------------------------------------------------------------------------
extern "C" void kernel_launch(void* const* d_in, const int* in_sizes, int n_in,
                              void* d_out, int out_size)
{
    const float* values = (const float*)d_in[0];
    const float* keys   = (const float*)d_in[1];
    const float* query  = (const float*)d_in[2];
    const float* Wv     = (const float*)d_in[3];
    const float* Wk     = (const float*)d_in[4];
    const float* Wq     = (const float*)d_in[5];
    const float* Wo     = (const float*)d_in[6];
    const float* bo     = (const float*)d_in[7];
    float* out = (float*)d_out;

    proj_kernel<<<1024, 256>>>(query,  Wq, 0);
    proj_kernel<<<1024, 256>>>(keys,   Wk, 1);
    proj_kernel<<<1024, 256>>>(values, Wv, 2);

    const int FSMEM = (2 * KTILE + 2 * VTILE) * (int)sizeof(float);  // 71680
    static int configured = 0;
    if (!configured) {
        cudaFuncSetAttribute(flash4_kernel,
                             cudaFuncAttributeMaxDynamicSharedMemorySize, FSMEM);
        configured = 1;
    }
    dim3 fgrid(SS / 64, BB * HH);
    flash4_kernel<<<fgrid, 128, FSMEM>>>();

    dim3 ggrid((BB * SS) / 128, EE / 128);
    out_gemm_tc<<<ggrid, 256>>>(Wo, bo, out);
}